// round 3
// baseline (speedup 1.0000x reference)
#include <cuda_runtime.h>
#include <math.h>

#define IMG   512
#define PIX   (IMG * IMG)
#define NIMG  64
#define TX    128
#define RPB   64
#define NITER (RPB + 10)            // 74 streamed rows per block
#define NOUTER 7                    // 7*11 = 77 >= NITER
#define PADW  (TX + 12)
#define GX    (IMG / TX)            // 4
#define GY    (IMG / RPB)           // 8
#define GZ    (NIMG / 2)            // 32 image pairs (f32x2 packing)
#define NBLK  (GX * GY * GZ)        // 1024

typedef unsigned long long u64;

__device__ double g_part[NBLK];

static __device__ __forceinline__ u64 pk2(float a, float b) {
    u64 r; asm("mov.b64 %0, {%1, %2};" : "=l"(r) : "f"(a), "f"(b)); return r;
}
static __device__ __forceinline__ void unpk2(u64 v, float& a, float& b) {
    asm("mov.b64 {%0, %1}, %2;" : "=f"(a), "=f"(b) : "l"(v));
}
static __device__ __forceinline__ u64 f2add(u64 a, u64 b) {
    u64 d; asm("add.rn.f32x2 %0, %1, %2;" : "=l"(d) : "l"(a), "l"(b)); return d;
}
static __device__ __forceinline__ u64 f2mul(u64 a, u64 b) {
    u64 d; asm("mul.rn.f32x2 %0, %1, %2;" : "=l"(d) : "l"(a), "l"(b)); return d;
}
static __device__ __forceinline__ u64 f2fma(u64 a, u64 b, u64 c) {
    u64 d; asm("fma.rn.f32x2 %0, %1, %2, %3;" : "=l"(d) : "l"(a), "l"(b), "l"(c)); return d;
}

// Load one column of one row for both image pairs; compute derived channels.
static __device__ __forceinline__ void ldcol(
    const float* __restrict__ p0, const float* __restrict__ p1,
    const float* __restrict__ g0, const float* __restrict__ g1,
    int off, bool ok, u64& P, u64& G, u64& S, u64& X)
{
    float a = ok ? __ldg(p0 + off) : 0.f;
    float b = ok ? __ldg(p1 + off) : 0.f;
    float c = ok ? __ldg(g0 + off) : 0.f;
    float d = ok ? __ldg(g1 + off) : 0.f;
    P = pk2(a, b);
    G = pk2(c, d);
    S = f2fma(G, G, f2mul(P, P));   // p^2 + g^2
    X = f2mul(P, G);                // p * g
}

__global__ void __launch_bounds__(TX, 3) ssim_main(
    const float* __restrict__ pred, const float* __restrict__ gt)
{
    // Raw tile: (p_im0, p_im1, g_im0, g_im1); derived tile: (s_im0, s_im1, x_im0, x_im1)
    __shared__ float4 sv[2][PADW];
    __shared__ float4 sq[2][PADW];
    __shared__ float wred[TX / 32];

    const int tid = threadIdx.x;
    const int cx  = blockIdx.x * TX;
    const int ry0 = blockIdx.y * RPB;
    const int im0 = blockIdx.z;

    const float* p0 = pred + (size_t)im0 * PIX;
    const float* p1 = pred + (size_t)(im0 + NIMG / 2) * PIX;
    const float* g0 = gt   + (size_t)im0 * PIX;
    const float* g1 = gt   + (size_t)(im0 + NIMG / 2) * PIX;

    // Gaussian 1D weights (sigma = 11/6, normalized)
    float w[6];
    {
        const float sig = 11.0f / 6.0f;
        const float inv = 1.0f / (2.0f * sig * sig);
        float e[6];
        #pragma unroll
        for (int d = 0; d < 6; ++d) e[d] = expf(-(float)(d * d) * inv);
        float s = e[0] + 2.f * (e[1] + e[2] + e[3] + e[4] + e[5]);
        #pragma unroll
        for (int d = 0; d < 6; ++d) w[d] = e[d] / s;
    }
    u64 w2[6];
    #pragma unroll
    for (int d = 0; d < 6; ++d) w2[d] = pk2(w[d], w[d]);

    const float C1 = 0.01f * 0.01f;
    const float C2 = 0.03f * 0.03f;
    const u64 c1_2  = pk2(C1, C1);
    const u64 c2_2  = pk2(C2, C2);
    const u64 c12_2 = pk2(C1 + C2, C1 + C2);
    const u64 two2  = pk2(2.f, 2.f);
    const u64 n2_2  = pk2(-2.f, -2.f);
    const u64 n1_2  = pk2(-1.f, -1.f);

    // 11-row ring buffers of horizontally-blurred channels (registers)
    u64 rP[11], rG[11], rS[11], rX[11];
    u64 acc = pk2(0.f, 0.f);

    const int cmain = cx + tid - 5;
    const int chalo = cx + TX + tid - 5;
    const bool cm_in = ((unsigned)cmain < IMG);
    const bool ch_in = ((unsigned)chalo < IMG) && (tid < 10);

    // distance-2 prefetch: two register sets (main + halo columns)
    u64 mP[2], mG[2], mS[2], mX[2];
    u64 hP_[2], hG_[2], hS_[2], hX_[2];

    #pragma unroll
    for (int s = 0; s < 2; ++s) {
        const int yin = ry0 - 5 + s;
        const bool rok = ((unsigned)yin < IMG);
        ldcol(p0, p1, g0, g1, yin * IMG + cmain, rok && cm_in,
              mP[s], mG[s], mS[s], mX[s]);
        ldcol(p0, p1, g0, g1, yin * IMG + chalo, rok && ch_in,
              hP_[s], hG_[s], hS_[s], hX_[s]);
    }

    for (int outer = 0; outer < NOUTER; ++outer) {
        #pragma unroll
        for (int k = 0; k < 11; ++k) {
            const int t = outer * 11 + k;
            const int buf = t & 1;
            if (t < NITER) {
                float a, b, c, d;
                unpk2(mP[buf], a, b); unpk2(mG[buf], c, d);
                sv[buf][tid] = make_float4(a, b, c, d);
                unpk2(mS[buf], a, b); unpk2(mX[buf], c, d);
                sq[buf][tid] = make_float4(a, b, c, d);
                if (tid < 10) {
                    unpk2(hP_[buf], a, b); unpk2(hG_[buf], c, d);
                    sv[buf][TX + tid] = make_float4(a, b, c, d);
                    unpk2(hS_[buf], a, b); unpk2(hX_[buf], c, d);
                    sq[buf][TX + tid] = make_float4(a, b, c, d);
                }
            }
            __syncthreads();
            if (t + 2 < NITER) {
                // prefetch row t+2 into the register set just freed
                const int yin = ry0 - 5 + t + 2;
                const bool rok = ((unsigned)yin < IMG);
                ldcol(p0, p1, g0, g1, yin * IMG + cmain, rok && cm_in,
                      mP[buf], mG[buf], mS[buf], mX[buf]);
                ldcol(p0, p1, g0, g1, yin * IMG + chalo, rok && ch_in,
                      hP_[buf], hG_[buf], hS_[buf], hX_[buf]);
            }
            if (t < NITER) {
                // ---- horizontal blur: 4 plain channels, symmetric taps ----
                const float4* V = &sv[buf][tid];
                const float4* Q = &sq[buf][tid];
                float4 cv = V[5], cq = Q[5];
                u64 hP = f2mul(pk2(cv.x, cv.y), w2[0]);
                u64 hG = f2mul(pk2(cv.z, cv.w), w2[0]);
                u64 hS = f2mul(pk2(cq.x, cq.y), w2[0]);
                u64 hX = f2mul(pk2(cq.z, cq.w), w2[0]);
                #pragma unroll
                for (int d = 1; d <= 5; ++d) {
                    float4 Lv = V[5 - d], Rv = V[5 + d];
                    float4 Lq = Q[5 - d], Rq = Q[5 + d];
                    hP = f2fma(f2add(pk2(Lv.x, Lv.y), pk2(Rv.x, Rv.y)), w2[d], hP);
                    hG = f2fma(f2add(pk2(Lv.z, Lv.w), pk2(Rv.z, Rv.w)), w2[d], hG);
                    hS = f2fma(f2add(pk2(Lq.x, Lq.y), pk2(Rq.x, Rq.y)), w2[d], hS);
                    hX = f2fma(f2add(pk2(Lq.z, Lq.w), pk2(Rq.z, Rq.w)), w2[d], hX);
                }
                rP[k] = hP; rG[k] = hG; rS[k] = hS; rX[k] = hX;

                if (t >= 10) {
                    // ---- vertical blur (ring slots constant-folded; split chains) ----
                    u64 m1, m2, sS, s12;
                    #define VS(j) (((k) + 6 + (j)) % 11)
                    #define VBLUR(dst, r)                                          \
                        { u64 pa = f2fma(f2add(r[VS(-1)], r[VS(1)]), w2[1],        \
                                         f2mul(r[VS(0)], w2[0]));                  \
                          pa = f2fma(f2add(r[VS(-3)], r[VS(3)]), w2[3], pa);       \
                          u64 pb = f2mul(f2add(r[VS(-2)], r[VS(2)]), w2[2]);       \
                          pb = f2fma(f2add(r[VS(-4)], r[VS(4)]), w2[4], pb);       \
                          pb = f2fma(f2add(r[VS(-5)], r[VS(5)]), w2[5], pb);       \
                          dst = f2add(pa, pb); }
                    VBLUR(m1,  rP);
                    VBLUR(m2,  rG);
                    VBLUR(sS,  rS);
                    VBLUR(s12, rX);
                    #undef VBLUR
                    #undef VS

                    // ---- SSIM map value ----
                    u64 m12 = f2mul(m1, m2);
                    u64 A  = f2fma(m12, two2, c1_2);                    // 2 mu1 mu2 + C1
                    u64 B  = f2fma(s12, two2, f2fma(m12, n2_2, c2_2));  // 2 sigma12 + C2
                    u64 Cq = f2fma(m2, m2, f2fma(m1, m1, c1_2));        // mu1^2+mu2^2+C1
                    u64 Dq = f2fma(Cq, n1_2, f2add(sS, c12_2));         // sig1+sig2+C2
                    u64 num = f2mul(A, B);
                    u64 den = f2mul(Cq, Dq);
                    float na, nb, da, db;
                    unpk2(num, na, nb); unpk2(den, da, db);
                    acc = f2add(acc, pk2(__fdividef(na, da), __fdividef(nb, db)));
                }
            }
        }
    }

    // ---- block reduction (deterministic partials, no atomics) ----
    float a0, a1; unpk2(acc, a0, a1);
    float s = a0 + a1;
    #pragma unroll
    for (int o = 16; o > 0; o >>= 1) s += __shfl_xor_sync(0xffffffffu, s, o);
    if ((tid & 31) == 0) wred[tid >> 5] = s;
    __syncthreads();
    if (tid == 0) {
        double bs = 0.0;
        #pragma unroll
        for (int i = 0; i < TX / 32; ++i) bs += (double)wred[i];
        const int bid = blockIdx.x + GX * (blockIdx.y + GY * blockIdx.z);
        g_part[bid] = bs;
    }
}

__global__ void __launch_bounds__(NBLK) ssim_finalize(float* __restrict__ out)
{
    __shared__ double sh[NBLK / 32];
    const int tid = threadIdx.x;
    double v = g_part[tid];
    #pragma unroll
    for (int o = 16; o > 0; o >>= 1) v += __shfl_xor_sync(0xffffffffu, v, o);
    if ((tid & 31) == 0) sh[tid >> 5] = v;
    __syncthreads();
    if (tid < 32) {
        double v2 = sh[tid];
        #pragma unroll
        for (int o = 16; o > 0; o >>= 1) v2 += __shfl_xor_sync(0xffffffffu, v2, o);
        if (tid == 0)
            out[0] = (float)(1.0 - v2 / ((double)NIMG * (double)PIX));
    }
}

extern "C" void kernel_launch(void* const* d_in, const int* in_sizes, int n_in,
                              void* d_out, int out_size)
{
    const float* pred = (const float*)d_in[0];
    const float* gt   = (const float*)d_in[1];
    float* out = (float*)d_out;

    dim3 grid(GX, GY, GZ);
    ssim_main<<<grid, TX>>>(pred, gt);
    ssim_finalize<<<1, NBLK>>>(out);
}

// round 4
// speedup vs baseline: 2.0955x; 2.0955x over previous
#include <cuda_runtime.h>
#include <math.h>

#define IMG   512
#define PIX   (IMG * IMG)
#define NIMG  64
#define TX    128
#define RPB   64
#define NITER (RPB + 10)            // 74 streamed rows per block
#define NOUTER 7                    // 7*11 = 77 >= NITER
#define PADW  (TX + 12)
#define GX    (IMG / TX)            // 4
#define GY    (IMG / RPB)           // 8
#define GZ    (NIMG / 2)            // 32 image pairs (f32x2 packing)
#define NBLK  (GX * GY * GZ)        // 1024

typedef unsigned long long u64;

__device__ double g_part[NBLK];

static __device__ __forceinline__ u64 pk2(float a, float b) {
    u64 r; asm("mov.b64 %0, {%1, %2};" : "=l"(r) : "f"(a), "f"(b)); return r;
}
static __device__ __forceinline__ void unpk2(u64 v, float& a, float& b) {
    asm("mov.b64 {%0, %1}, %2;" : "=f"(a), "=f"(b) : "l"(v));
}
static __device__ __forceinline__ u64 f2add(u64 a, u64 b) {
    u64 d; asm("add.rn.f32x2 %0, %1, %2;" : "=l"(d) : "l"(a), "l"(b)); return d;
}
static __device__ __forceinline__ u64 f2mul(u64 a, u64 b) {
    u64 d; asm("mul.rn.f32x2 %0, %1, %2;" : "=l"(d) : "l"(a), "l"(b)); return d;
}
static __device__ __forceinline__ u64 f2fma(u64 a, u64 b, u64 c) {
    u64 d; asm("fma.rn.f32x2 %0, %1, %2, %3;" : "=l"(d) : "l"(a), "l"(b), "l"(c)); return d;
}

__global__ void __launch_bounds__(TX, 3) ssim_main(
    const float* __restrict__ pred, const float* __restrict__ gt)
{
    // Raw tile: (p0, p1, g0, g1); derived tile: (p0^2+g0^2, p1^2+g1^2, p0*g0, p1*g1)
    __shared__ float4 sv[2][PADW];
    __shared__ float4 sq[2][PADW];
    __shared__ float wred[TX / 32];

    const int tid = threadIdx.x;
    const int cx  = blockIdx.x * TX;
    const int ry0 = blockIdx.y * RPB;
    const int im0 = blockIdx.z;

    const float* p0 = pred + (size_t)im0 * PIX;
    const float* p1 = pred + (size_t)(im0 + NIMG / 2) * PIX;
    const float* g0 = gt   + (size_t)im0 * PIX;
    const float* g1 = gt   + (size_t)(im0 + NIMG / 2) * PIX;

    // Gaussian 1D weights (sigma = 11/6, normalized) — same math as reference
    float w[6];
    {
        const float sig = 11.0f / 6.0f;
        const float inv = 1.0f / (2.0f * sig * sig);
        float e[6];
        #pragma unroll
        for (int d = 0; d < 6; ++d) e[d] = expf(-(float)(d * d) * inv);
        float s = e[0] + 2.f * (e[1] + e[2] + e[3] + e[4] + e[5]);
        #pragma unroll
        for (int d = 0; d < 6; ++d) w[d] = e[d] / s;
    }
    u64 w2[6];
    #pragma unroll
    for (int d = 0; d < 6; ++d) w2[d] = pk2(w[d], w[d]);

    const float C1 = 0.01f * 0.01f;
    const float C2 = 0.03f * 0.03f;
    const u64 c1_2  = pk2(C1, C1);
    const u64 c2_2  = pk2(C2, C2);
    const u64 c12_2 = pk2(C1 + C2, C1 + C2);
    const u64 two2  = pk2(2.f, 2.f);
    const u64 n2_2  = pk2(-2.f, -2.f);
    const u64 n1_2  = pk2(-1.f, -1.f);

    // 11-row ring buffers of horizontally-blurred channels (registers)
    u64 rP[11], rG[11], rS[11], rX[11];
    u64 acc = pk2(0.f, 0.f);

    const int cmain = cx + tid - 5;
    const int chalo = cx + TX + tid - 5;
    const bool cm_in = ((unsigned)cmain < IMG);
    const bool ch_in = ((unsigned)chalo < IMG) && (tid < 10);

    float pm0, pm1, gm0, gm1;   // prefetched main column (raw)
    float ph0, ph1, gh0, gh1;   // prefetched halo column (tid < 10)

    // prefetch first row (t = 0)
    {
        const int yin = ry0 - 5;
        const bool rok = ((unsigned)yin < IMG);
        const bool ok  = rok && cm_in;
        const int off = yin * IMG + cmain;
        pm0 = ok ? p0[off] : 0.f;  pm1 = ok ? p1[off] : 0.f;
        gm0 = ok ? g0[off] : 0.f;  gm1 = ok ? g1[off] : 0.f;
        const bool ok2 = rok && ch_in;
        const int off2 = yin * IMG + chalo;
        ph0 = ok2 ? p0[off2] : 0.f;  ph1 = ok2 ? p1[off2] : 0.f;
        gh0 = ok2 ? g0[off2] : 0.f;  gh1 = ok2 ? g1[off2] : 0.f;
    }

    for (int outer = 0; outer < NOUTER; ++outer) {
        #pragma unroll
        for (int k = 0; k < 11; ++k) {
            const int t = outer * 11 + k;
            const int buf = t & 1;
            if (t < NITER) {
                // store raw + derived tiles (derived computed transiently)
                sv[buf][tid] = make_float4(pm0, pm1, gm0, gm1);
                sq[buf][tid] = make_float4(fmaf(pm0, pm0, gm0 * gm0),
                                           fmaf(pm1, pm1, gm1 * gm1),
                                           pm0 * gm0, pm1 * gm1);
                if (tid < 10) {
                    sv[buf][TX + tid] = make_float4(ph0, ph1, gh0, gh1);
                    sq[buf][TX + tid] = make_float4(fmaf(ph0, ph0, gh0 * gh0),
                                                    fmaf(ph1, ph1, gh1 * gh1),
                                                    ph0 * gh0, ph1 * gh1);
                }
            }
            // prefetch next row BEFORE the barrier: the barrier wait plus the
            // whole row's compute covers the DRAM latency. STS above already
            // consumed the old register values.
            if (t + 1 < NITER) {
                const int yin = ry0 - 5 + t + 1;
                const bool rok = ((unsigned)yin < IMG);
                const bool ok  = rok && cm_in;
                const int off = yin * IMG + cmain;
                pm0 = ok ? p0[off] : 0.f;  pm1 = ok ? p1[off] : 0.f;
                gm0 = ok ? g0[off] : 0.f;  gm1 = ok ? g1[off] : 0.f;
                const bool ok2 = rok && ch_in;
                const int off2 = yin * IMG + chalo;
                ph0 = ok2 ? p0[off2] : 0.f;  ph1 = ok2 ? p1[off2] : 0.f;
                gh0 = ok2 ? g0[off2] : 0.f;  gh1 = ok2 ? g1[off2] : 0.f;
            }
            __syncthreads();
            if (t < NITER) {
                // ---- horizontal blur: 4 uniform channels, symmetric taps ----
                const float4* V = &sv[buf][tid];
                const float4* Q = &sq[buf][tid];
                float4 cv = V[5], cq = Q[5];
                u64 hP = f2mul(pk2(cv.x, cv.y), w2[0]);
                u64 hG = f2mul(pk2(cv.z, cv.w), w2[0]);
                u64 hS = f2mul(pk2(cq.x, cq.y), w2[0]);
                u64 hX = f2mul(pk2(cq.z, cq.w), w2[0]);
                #pragma unroll
                for (int d = 1; d <= 5; ++d) {
                    float4 Lv = V[5 - d], Rv = V[5 + d];
                    float4 Lq = Q[5 - d], Rq = Q[5 + d];
                    hP = f2fma(f2add(pk2(Lv.x, Lv.y), pk2(Rv.x, Rv.y)), w2[d], hP);
                    hG = f2fma(f2add(pk2(Lv.z, Lv.w), pk2(Rv.z, Rv.w)), w2[d], hG);
                    hS = f2fma(f2add(pk2(Lq.x, Lq.y), pk2(Rq.x, Rq.y)), w2[d], hS);
                    hX = f2fma(f2add(pk2(Lq.z, Lq.w), pk2(Rq.z, Rq.w)), w2[d], hX);
                }
                rP[k] = hP; rG[k] = hG; rS[k] = hS; rX[k] = hX;

                if (t >= 10) {
                    // ---- vertical blur (ring slots constant-folded; split chains) ----
                    u64 m1, m2, sS, s12;
                    #define VS(j) (((k) + 6 + (j)) % 11)
                    #define VBLUR(dst, r)                                          \
                        { u64 pa = f2fma(f2add(r[VS(-1)], r[VS(1)]), w2[1],        \
                                         f2mul(r[VS(0)], w2[0]));                  \
                          pa = f2fma(f2add(r[VS(-3)], r[VS(3)]), w2[3], pa);       \
                          u64 pb = f2mul(f2add(r[VS(-2)], r[VS(2)]), w2[2]);       \
                          pb = f2fma(f2add(r[VS(-4)], r[VS(4)]), w2[4], pb);       \
                          pb = f2fma(f2add(r[VS(-5)], r[VS(5)]), w2[5], pb);       \
                          dst = f2add(pa, pb); }
                    VBLUR(m1,  rP);
                    VBLUR(m2,  rG);
                    VBLUR(sS,  rS);
                    VBLUR(s12, rX);
                    #undef VBLUR
                    #undef VS

                    // ---- SSIM map value ----
                    u64 m12 = f2mul(m1, m2);
                    u64 A  = f2fma(m12, two2, c1_2);                    // 2 mu1 mu2 + C1
                    u64 B  = f2fma(s12, two2, f2fma(m12, n2_2, c2_2));  // 2 sigma12 + C2
                    u64 Cq = f2fma(m2, m2, f2fma(m1, m1, c1_2));        // mu1^2+mu2^2+C1
                    u64 Dq = f2fma(Cq, n1_2, f2add(sS, c12_2));         // sig1+sig2+C2
                    u64 num = f2mul(A, B);
                    u64 den = f2mul(Cq, Dq);
                    float na, nb, da, db;
                    unpk2(num, na, nb); unpk2(den, da, db);
                    acc = f2add(acc, pk2(__fdividef(na, da), __fdividef(nb, db)));
                }
            }
        }
    }

    // ---- block reduction (deterministic partials, no atomics) ----
    float a0, a1; unpk2(acc, a0, a1);
    float s = a0 + a1;
    #pragma unroll
    for (int o = 16; o > 0; o >>= 1) s += __shfl_xor_sync(0xffffffffu, s, o);
    if ((tid & 31) == 0) wred[tid >> 5] = s;
    __syncthreads();
    if (tid == 0) {
        double bs = 0.0;
        #pragma unroll
        for (int i = 0; i < TX / 32; ++i) bs += (double)wred[i];
        const int bid = blockIdx.x + GX * (blockIdx.y + GY * blockIdx.z);
        g_part[bid] = bs;
    }
}

__global__ void __launch_bounds__(NBLK) ssim_finalize(float* __restrict__ out)
{
    __shared__ double sh[NBLK / 32];
    const int tid = threadIdx.x;
    double v = g_part[tid];
    #pragma unroll
    for (int o = 16; o > 0; o >>= 1) v += __shfl_xor_sync(0xffffffffu, v, o);
    if ((tid & 31) == 0) sh[tid >> 5] = v;
    __syncthreads();
    if (tid < 32) {
        double v2 = sh[tid];
        #pragma unroll
        for (int o = 16; o > 0; o >>= 1) v2 += __shfl_xor_sync(0xffffffffu, v2, o);
        if (tid == 0)
            out[0] = (float)(1.0 - v2 / ((double)NIMG * (double)PIX));
    }
}

extern "C" void kernel_launch(void* const* d_in, const int* in_sizes, int n_in,
                              void* d_out, int out_size)
{
    const float* pred = (const float*)d_in[0];
    const float* gt   = (const float*)d_in[1];
    float* out = (float*)d_out;

    dim3 grid(GX, GY, GZ);
    ssim_main<<<grid, TX>>>(pred, gt);
    ssim_finalize<<<1, NBLK>>>(out);
}

// round 5
// speedup vs baseline: 2.1618x; 1.0316x over previous
#include <cuda_runtime.h>
#include <math.h>

#define IMG   512
#define PIX   (IMG * IMG)
#define NIMG  64
#define TX    128
#define RPB   64
#define NITER (RPB + 10)            // 74 streamed rows per block
#define NPAIR (NITER / 2)           // 37 row pairs
#define PADW  (TX + 12)
#define GX    (IMG / TX)            // 4
#define GY    (IMG / RPB)           // 8
#define GZ    (NIMG / 2)            // 32 image pairs (f32x2 packing)
#define NBLK  (GX * GY * GZ)        // 1024

typedef unsigned long long u64;

__device__ double g_part[NBLK];
__device__ int    g_cnt;            // zero-initialized; self-resets each launch

static __device__ __forceinline__ u64 pk2(float a, float b) {
    u64 r; asm("mov.b64 %0, {%1, %2};" : "=l"(r) : "f"(a), "f"(b)); return r;
}
static __device__ __forceinline__ void unpk2(u64 v, float& a, float& b) {
    asm("mov.b64 {%0, %1}, %2;" : "=f"(a), "=f"(b) : "l"(v));
}
static __device__ __forceinline__ u64 f2add(u64 a, u64 b) {
    u64 d; asm("add.rn.f32x2 %0, %1, %2;" : "=l"(d) : "l"(a), "l"(b)); return d;
}
static __device__ __forceinline__ u64 f2mul(u64 a, u64 b) {
    u64 d; asm("mul.rn.f32x2 %0, %1, %2;" : "=l"(d) : "l"(a), "l"(b)); return d;
}
static __device__ __forceinline__ u64 f2fma(u64 a, u64 b, u64 c) {
    u64 d; asm("fma.rn.f32x2 %0, %1, %2, %3;" : "=l"(d) : "l"(a), "l"(b), "l"(c)); return d;
}

__global__ void __launch_bounds__(TX, 3) ssim_main(
    const float* __restrict__ pred, const float* __restrict__ gt,
    float* __restrict__ out)
{
    // Double-buffered 2-row tiles. Raw: (p0,p1,g0,g1); derived: (p^2+g^2 x2, p*g x2)
    __shared__ float4 sv[2][2][PADW];
    __shared__ float4 sq[2][2][PADW];
    __shared__ float wred[TX / 32];
    __shared__ int   slast;

    const int tid = threadIdx.x;
    const int cx  = blockIdx.x * TX;
    const int ry0 = blockIdx.y * RPB;
    const int im0 = blockIdx.z;

    const float* p0 = pred + (size_t)im0 * PIX;
    const float* p1 = pred + (size_t)(im0 + NIMG / 2) * PIX;
    const float* g0 = gt   + (size_t)im0 * PIX;
    const float* g1 = gt   + (size_t)(im0 + NIMG / 2) * PIX;

    // Gaussian 1D weights (sigma = 11/6, normalized) — same math as reference
    float w[6];
    {
        const float sig = 11.0f / 6.0f;
        const float inv = 1.0f / (2.0f * sig * sig);
        float e[6];
        #pragma unroll
        for (int d = 0; d < 6; ++d) e[d] = expf(-(float)(d * d) * inv);
        float s = e[0] + 2.f * (e[1] + e[2] + e[3] + e[4] + e[5]);
        #pragma unroll
        for (int d = 0; d < 6; ++d) w[d] = e[d] / s;
    }
    u64 w2[6];
    #pragma unroll
    for (int d = 0; d < 6; ++d) w2[d] = pk2(w[d], w[d]);

    const float C1 = 0.01f * 0.01f;
    const float C2 = 0.03f * 0.03f;
    const u64 c1_2  = pk2(C1, C1);
    const u64 c2_2  = pk2(C2, C2);
    const u64 c12_2 = pk2(C1 + C2, C1 + C2);
    const u64 two2  = pk2(2.f, 2.f);
    const u64 n2_2  = pk2(-2.f, -2.f);
    const u64 n1_2  = pk2(-1.f, -1.f);

    // 11-row ring buffers of horizontally-blurred channels (registers)
    u64 rP[11], rG[11], rS[11], rX[11];
    u64 acc0 = pk2(0.f, 0.f);
    u64 acc1 = pk2(0.f, 0.f);

    const int cmain = cx + tid - 5;
    const int chalo = cx + TX + tid - 5;
    const bool cm_in = ((unsigned)cmain < IMG);
    const bool ch_in = ((unsigned)chalo < IMG) && (tid < 10);

    // prefetch register sets for two rows (A = even row, B = odd row)
    float pmA0, pmA1, gmA0, gmA1, phA0, phA1, ghA0, ghA1;
    float pmB0, pmB1, gmB0, gmB1, phB0, phB1, ghB0, ghB1;

    #define LOADROW(sfx, T)                                                     \
        {                                                                       \
            const int yin = ry0 - 5 + (T);                                      \
            const bool rok = ((unsigned)yin < IMG);                             \
            const bool ok  = rok && cm_in;                                      \
            const int off = yin * IMG + cmain;                                  \
            pm##sfx##0 = ok ? p0[off] : 0.f;  pm##sfx##1 = ok ? p1[off] : 0.f;  \
            gm##sfx##0 = ok ? g0[off] : 0.f;  gm##sfx##1 = ok ? g1[off] : 0.f;  \
            const bool ok2 = rok && ch_in;                                      \
            const int off2 = yin * IMG + chalo;                                 \
            ph##sfx##0 = ok2 ? p0[off2] : 0.f; ph##sfx##1 = ok2 ? p1[off2] : 0.f;\
            gh##sfx##0 = ok2 ? g0[off2] : 0.f; gh##sfx##1 = ok2 ? g1[off2] : 0.f;\
        }

    LOADROW(A, 0)
    LOADROW(B, 1)

    for (int outer = 0; outer < 4; ++outer) {
        #pragma unroll
        for (int j = 0; j < 11; ++j) {
            const int pair = outer * 11 + j;
            if (pair < NPAIR) {
                const int buf = pair & 1;
                // ---- store both rows (raw + transient derived) ----
                sv[buf][0][tid] = make_float4(pmA0, pmA1, gmA0, gmA1);
                sq[buf][0][tid] = make_float4(fmaf(pmA0, pmA0, gmA0 * gmA0),
                                              fmaf(pmA1, pmA1, gmA1 * gmA1),
                                              pmA0 * gmA0, pmA1 * gmA1);
                sv[buf][1][tid] = make_float4(pmB0, pmB1, gmB0, gmB1);
                sq[buf][1][tid] = make_float4(fmaf(pmB0, pmB0, gmB0 * gmB0),
                                              fmaf(pmB1, pmB1, gmB1 * gmB1),
                                              pmB0 * gmB0, pmB1 * gmB1);
                if (tid < 10) {
                    sv[buf][0][TX + tid] = make_float4(phA0, phA1, ghA0, ghA1);
                    sq[buf][0][TX + tid] = make_float4(fmaf(phA0, phA0, ghA0 * ghA0),
                                                       fmaf(phA1, phA1, ghA1 * ghA1),
                                                       phA0 * ghA0, phA1 * ghA1);
                    sv[buf][1][TX + tid] = make_float4(phB0, phB1, ghB0, ghB1);
                    sq[buf][1][TX + tid] = make_float4(fmaf(phB0, phB0, ghB0 * ghB0),
                                                       fmaf(phB1, phB1, ghB1 * ghB1),
                                                       phB0 * ghB0, phB1 * ghB1);
                }
                // ---- prefetch next pair (barrier + full pair compute covers DRAM) ----
                const int t0 = 2 * pair;
                if (t0 + 2 < NITER) LOADROW(A, t0 + 2)
                if (t0 + 3 < NITER) LOADROW(B, t0 + 3)
                __syncthreads();

                // ---- horizontal blur of both rows (constant ring slots) ----
                const int k0 = (2 * j) % 11;
                const int k1 = (2 * j + 1) % 11;
                #define HBLUR(ROW, KD)                                                      \
                    {                                                                       \
                        const float4* V = &sv[buf][ROW][tid];                               \
                        const float4* Q = &sq[buf][ROW][tid];                               \
                        float4 cv = V[5], cq = Q[5];                                        \
                        u64 hP = f2mul(pk2(cv.x, cv.y), w2[0]);                             \
                        u64 hG = f2mul(pk2(cv.z, cv.w), w2[0]);                             \
                        u64 hS = f2mul(pk2(cq.x, cq.y), w2[0]);                             \
                        u64 hX = f2mul(pk2(cq.z, cq.w), w2[0]);                             \
                        _Pragma("unroll")                                                   \
                        for (int d = 1; d <= 5; ++d) {                                      \
                            float4 Lv = V[5 - d], Rv = V[5 + d];                            \
                            float4 Lq = Q[5 - d], Rq = Q[5 + d];                            \
                            hP = f2fma(f2add(pk2(Lv.x, Lv.y), pk2(Rv.x, Rv.y)), w2[d], hP); \
                            hG = f2fma(f2add(pk2(Lv.z, Lv.w), pk2(Rv.z, Rv.w)), w2[d], hG); \
                            hS = f2fma(f2add(pk2(Lq.x, Lq.y), pk2(Rq.x, Rq.y)), w2[d], hS); \
                            hX = f2fma(f2add(pk2(Lq.z, Lq.w), pk2(Rq.z, Rq.w)), w2[d], hX); \
                        }                                                                   \
                        rP[KD] = hP; rG[KD] = hG; rS[KD] = hS; rX[KD] = hX;                 \
                    }
                HBLUR(0, k0)
                HBLUR(1, k1)
                #undef HBLUR

                if (pair >= 5) {
                    // ---- vertical blur + SSIM for both rows ----
                    #define VS(K, JJ) (((K) + 6 + (JJ) + 11) % 11)
                    #define VBLUR(dst, r, K)                                           \
                        { u64 pa = f2fma(f2add(r[VS(K,-1)], r[VS(K,1)]), w2[1],        \
                                         f2mul(r[VS(K,0)], w2[0]));                    \
                          pa = f2fma(f2add(r[VS(K,-3)], r[VS(K,3)]), w2[3], pa);       \
                          u64 pb = f2mul(f2add(r[VS(K,-2)], r[VS(K,2)]), w2[2]);       \
                          pb = f2fma(f2add(r[VS(K,-4)], r[VS(K,4)]), w2[4], pb);       \
                          pb = f2fma(f2add(r[VS(K,-5)], r[VS(K,5)]), w2[5], pb);       \
                          dst = f2add(pa, pb); }
                    #define SSIMROW(K, ACC)                                            \
                        { u64 m1, m2, sS, s12;                                         \
                          VBLUR(m1,  rP, K); VBLUR(m2,  rG, K);                        \
                          VBLUR(sS,  rS, K); VBLUR(s12, rX, K);                        \
                          u64 m12 = f2mul(m1, m2);                                     \
                          u64 A  = f2fma(m12, two2, c1_2);                             \
                          u64 B  = f2fma(s12, two2, f2fma(m12, n2_2, c2_2));           \
                          u64 Cq = f2fma(m2, m2, f2fma(m1, m1, c1_2));                 \
                          u64 Dq = f2fma(Cq, n1_2, f2add(sS, c12_2));                  \
                          u64 num = f2mul(A, B);                                       \
                          u64 den = f2mul(Cq, Dq);                                     \
                          float na, nb, da, db;                                        \
                          unpk2(num, na, nb); unpk2(den, da, db);                      \
                          ACC = f2add(ACC, pk2(__fdividef(na, da),                     \
                                               __fdividef(nb, db))); }
                    SSIMROW(k0, acc0)
                    SSIMROW(k1, acc1)
                    #undef SSIMROW
                    #undef VBLUR
                    #undef VS
                }
            }
        }
    }
    #undef LOADROW

    // ---- block reduction (deterministic partials, no float atomics) ----
    u64 accT = f2add(acc0, acc1);
    float a0, a1; unpk2(accT, a0, a1);
    float s = a0 + a1;
    #pragma unroll
    for (int o = 16; o > 0; o >>= 1) s += __shfl_xor_sync(0xffffffffu, s, o);
    if ((tid & 31) == 0) wred[tid >> 5] = s;
    __syncthreads();
    if (tid == 0) {
        double bs = 0.0;
        #pragma unroll
        for (int i = 0; i < TX / 32; ++i) bs += (double)wred[i];
        const int bid = blockIdx.x + GX * (blockIdx.y + GY * blockIdx.z);
        g_part[bid] = bs;
        __threadfence();
        int old = atomicAdd(&g_cnt, 1);
        slast = (old == NBLK - 1) ? 1 : 0;
    }
    __syncthreads();

    // ---- last block finalizes (deterministic fixed-order double sum) ----
    if (slast) {
        __threadfence();
        double v = 0.0;
        #pragma unroll
        for (int i = 0; i < NBLK / TX; ++i)
            v += g_part[tid + i * TX];
        #pragma unroll
        for (int o = 16; o > 0; o >>= 1) v += __shfl_xor_sync(0xffffffffu, v, o);
        __shared__ double sh[TX / 32];
        if ((tid & 31) == 0) sh[tid >> 5] = v;
        __syncthreads();
        if (tid == 0) {
            double tot = 0.0;
            #pragma unroll
            for (int i = 0; i < TX / 32; ++i) tot += sh[i];
            out[0] = (float)(1.0 - tot / ((double)NIMG * (double)PIX));
            g_cnt = 0;   // self-reset for graph replay
        }
    }
}

extern "C" void kernel_launch(void* const* d_in, const int* in_sizes, int n_in,
                              void* d_out, int out_size)
{
    const float* pred = (const float*)d_in[0];
    const float* gt   = (const float*)d_in[1];
    float* out = (float*)d_out;

    dim3 grid(GX, GY, GZ);
    ssim_main<<<grid, TX>>>(pred, gt, out);
}

// round 6
// speedup vs baseline: 2.3222x; 1.0742x over previous
#include <cuda_runtime.h>
#include <math.h>

#define IMG   512
#define PIX   (IMG * IMG)
#define NIMG  64
#define TX    128
#define RPB   64
#define NITER (RPB + 10)            // 74 streamed rows per block
#define NPAIR (NITER / 2)           // 37 row pairs
#define PADW  (TX + 12)
#define GX    (IMG / TX)            // 4
#define GY    (IMG / RPB)           // 8
#define GZ    (NIMG / 2)            // 32 image pairs (f32x2 packing)
#define NBLK  (GX * GY * GZ)        // 1024

typedef unsigned long long u64;

__device__ double g_part[NBLK];
__device__ int    g_cnt;            // zero-initialized; self-resets each launch

static __device__ __forceinline__ u64 pk2(float a, float b) {
    u64 r; asm("mov.b64 %0, {%1, %2};" : "=l"(r) : "f"(a), "f"(b)); return r;
}
static __device__ __forceinline__ void unpk2(u64 v, float& a, float& b) {
    asm("mov.b64 {%0, %1}, %2;" : "=f"(a), "=f"(b) : "l"(v));
}
static __device__ __forceinline__ u64 f2add(u64 a, u64 b) {
    u64 d; asm("add.rn.f32x2 %0, %1, %2;" : "=l"(d) : "l"(a), "l"(b)); return d;
}
static __device__ __forceinline__ u64 f2mul(u64 a, u64 b) {
    u64 d; asm("mul.rn.f32x2 %0, %1, %2;" : "=l"(d) : "l"(a), "l"(b)); return d;
}
static __device__ __forceinline__ u64 f2fma(u64 a, u64 b, u64 c) {
    u64 d; asm("fma.rn.f32x2 %0, %1, %2, %3;" : "=l"(d) : "l"(a), "l"(b), "l"(c)); return d;
}

__global__ void __launch_bounds__(TX, 3) ssim_main(
    const float* __restrict__ pred, const float* __restrict__ gt,
    float* __restrict__ out)
{
    // Double-buffered 2-row RAW tiles only: (p_im0, p_im1, g_im0, g_im1).
    // Derived channels (p^2+g^2, p*g) are recomputed in registers during hblur
    // — trades fma ops for a 2x cut in LDS crossbar traffic (the measured
    // bottleneck: L1 79% vs fma 40% in R5).
    __shared__ float4 sv[2][2][PADW];
    __shared__ float wred[TX / 32];
    __shared__ int   slast;

    const int tid = threadIdx.x;
    const int cx  = blockIdx.x * TX;
    const int ry0 = blockIdx.y * RPB;
    const int im0 = blockIdx.z;

    const float* p0 = pred + (size_t)im0 * PIX;
    const float* p1 = pred + (size_t)(im0 + NIMG / 2) * PIX;
    const float* g0 = gt   + (size_t)im0 * PIX;
    const float* g1 = gt   + (size_t)(im0 + NIMG / 2) * PIX;

    // Gaussian 1D weights (sigma = 11/6, normalized) — same math as reference
    float w[6];
    {
        const float sig = 11.0f / 6.0f;
        const float inv = 1.0f / (2.0f * sig * sig);
        float e[6];
        #pragma unroll
        for (int d = 0; d < 6; ++d) e[d] = expf(-(float)(d * d) * inv);
        float s = e[0] + 2.f * (e[1] + e[2] + e[3] + e[4] + e[5]);
        #pragma unroll
        for (int d = 0; d < 6; ++d) w[d] = e[d] / s;
    }
    u64 w2[6];
    #pragma unroll
    for (int d = 0; d < 6; ++d) w2[d] = pk2(w[d], w[d]);

    const float C1 = 0.01f * 0.01f;
    const float C2 = 0.03f * 0.03f;
    const u64 c1_2  = pk2(C1, C1);
    const u64 c2_2  = pk2(C2, C2);
    const u64 c12_2 = pk2(C1 + C2, C1 + C2);
    const u64 two2  = pk2(2.f, 2.f);
    const u64 n2_2  = pk2(-2.f, -2.f);
    const u64 n1_2  = pk2(-1.f, -1.f);

    // 11-row ring buffers of horizontally-blurred channels (registers)
    u64 rP[11], rG[11], rS[11], rX[11];
    u64 acc0 = pk2(0.f, 0.f);
    u64 acc1 = pk2(0.f, 0.f);

    const int cmain = cx + tid - 5;
    const int chalo = cx + TX + tid - 5;
    const bool cm_in = ((unsigned)cmain < IMG);
    const bool ch_in = ((unsigned)chalo < IMG) && (tid < 10);

    // prefetch register sets for two rows (A = even row, B = odd row)
    float pmA0, pmA1, gmA0, gmA1, phA0, phA1, ghA0, ghA1;
    float pmB0, pmB1, gmB0, gmB1, phB0, phB1, ghB0, ghB1;

    #define LOADROW(sfx, T)                                                     \
        {                                                                       \
            const int yin = ry0 - 5 + (T);                                      \
            const bool rok = ((unsigned)yin < IMG);                             \
            const bool ok  = rok && cm_in;                                      \
            const int off = yin * IMG + cmain;                                  \
            pm##sfx##0 = ok ? p0[off] : 0.f;  pm##sfx##1 = ok ? p1[off] : 0.f;  \
            gm##sfx##0 = ok ? g0[off] : 0.f;  gm##sfx##1 = ok ? g1[off] : 0.f;  \
            const bool ok2 = rok && ch_in;                                      \
            const int off2 = yin * IMG + chalo;                                 \
            ph##sfx##0 = ok2 ? p0[off2] : 0.f; ph##sfx##1 = ok2 ? p1[off2] : 0.f;\
            gh##sfx##0 = ok2 ? g0[off2] : 0.f; gh##sfx##1 = ok2 ? g1[off2] : 0.f;\
        }

    LOADROW(A, 0)
    LOADROW(B, 1)

    for (int outer = 0; outer < 4; ++outer) {
        #pragma unroll
        for (int j = 0; j < 11; ++j) {
            const int pair = outer * 11 + j;
            if (pair < NPAIR) {
                const int buf = pair & 1;
                // ---- store both raw rows ----
                sv[buf][0][tid] = make_float4(pmA0, pmA1, gmA0, gmA1);
                sv[buf][1][tid] = make_float4(pmB0, pmB1, gmB0, gmB1);
                if (tid < 10) {
                    sv[buf][0][TX + tid] = make_float4(phA0, phA1, ghA0, ghA1);
                    sv[buf][1][TX + tid] = make_float4(phB0, phB1, ghB0, ghB1);
                }
                // ---- prefetch next pair (barrier + pair compute covers DRAM) ----
                const int t0 = 2 * pair;
                if (t0 + 2 < NITER) LOADROW(A, t0 + 2)
                if (t0 + 3 < NITER) LOADROW(B, t0 + 3)
                __syncthreads();

                // ---- horizontal blur of both rows; derived channels recomputed ----
                const int k0 = (2 * j) % 11;
                const int k1 = (2 * j + 1) % 11;
                #define HBLUR(ROW, KD)                                                      \
                    {                                                                       \
                        const float4* V = &sv[buf][ROW][tid];                               \
                        float4 cv = V[5];                                                   \
                        u64 pc = pk2(cv.x, cv.y), gc = pk2(cv.z, cv.w);                     \
                        u64 hP = f2mul(pc, w2[0]);                                          \
                        u64 hG = f2mul(gc, w2[0]);                                          \
                        u64 hS = f2mul(f2fma(gc, gc, f2mul(pc, pc)), w2[0]);                \
                        u64 hX = f2mul(f2mul(pc, gc), w2[0]);                               \
                        _Pragma("unroll")                                                   \
                        for (int d = 1; d <= 5; ++d) {                                      \
                            float4 Lv = V[5 - d], Rv = V[5 + d];                            \
                            u64 pl = pk2(Lv.x, Lv.y), gl = pk2(Lv.z, Lv.w);                 \
                            u64 pr = pk2(Rv.x, Rv.y), gr = pk2(Rv.z, Rv.w);                 \
                            hP = f2fma(f2add(pl, pr), w2[d], hP);                           \
                            hG = f2fma(f2add(gl, gr), w2[d], hG);                           \
                            u64 ss = f2fma(pr, pr, f2mul(pl, pl));                          \
                            ss = f2fma(gl, gl, ss);                                         \
                            ss = f2fma(gr, gr, ss);                                         \
                            hS = f2fma(ss, w2[d], hS);                                      \
                            hX = f2fma(f2fma(pr, gr, f2mul(pl, gl)), w2[d], hX);            \
                        }                                                                   \
                        rP[KD] = hP; rG[KD] = hG; rS[KD] = hS; rX[KD] = hX;                 \
                    }
                HBLUR(0, k0)
                HBLUR(1, k1)
                #undef HBLUR

                if (pair >= 5) {
                    // ---- vertical blur + SSIM for both rows ----
                    #define VS(K, JJ) (((K) + 6 + (JJ) + 11) % 11)
                    #define VBLUR(dst, r, K)                                           \
                        { u64 pa = f2fma(f2add(r[VS(K,-1)], r[VS(K,1)]), w2[1],        \
                                         f2mul(r[VS(K,0)], w2[0]));                    \
                          pa = f2fma(f2add(r[VS(K,-3)], r[VS(K,3)]), w2[3], pa);       \
                          u64 pb = f2mul(f2add(r[VS(K,-2)], r[VS(K,2)]), w2[2]);       \
                          pb = f2fma(f2add(r[VS(K,-4)], r[VS(K,4)]), w2[4], pb);       \
                          pb = f2fma(f2add(r[VS(K,-5)], r[VS(K,5)]), w2[5], pb);       \
                          dst = f2add(pa, pb); }
                    #define SSIMROW(K, ACC)                                            \
                        { u64 m1, m2, sS, s12;                                         \
                          VBLUR(m1,  rP, K); VBLUR(m2,  rG, K);                        \
                          VBLUR(sS,  rS, K); VBLUR(s12, rX, K);                        \
                          u64 m12 = f2mul(m1, m2);                                     \
                          u64 A  = f2fma(m12, two2, c1_2);                             \
                          u64 B  = f2fma(s12, two2, f2fma(m12, n2_2, c2_2));           \
                          u64 Cq = f2fma(m2, m2, f2fma(m1, m1, c1_2));                 \
                          u64 Dq = f2fma(Cq, n1_2, f2add(sS, c12_2));                  \
                          u64 num = f2mul(A, B);                                       \
                          u64 den = f2mul(Cq, Dq);                                     \
                          float na, nb, da, db;                                        \
                          unpk2(num, na, nb); unpk2(den, da, db);                      \
                          ACC = f2add(ACC, pk2(__fdividef(na, da),                     \
                                               __fdividef(nb, db))); }
                    SSIMROW(k0, acc0)
                    SSIMROW(k1, acc1)
                    #undef SSIMROW
                    #undef VBLUR
                    #undef VS
                }
            }
        }
    }
    #undef LOADROW

    // ---- block reduction (deterministic partials, no float atomics) ----
    u64 accT = f2add(acc0, acc1);
    float a0, a1; unpk2(accT, a0, a1);
    float s = a0 + a1;
    #pragma unroll
    for (int o = 16; o > 0; o >>= 1) s += __shfl_xor_sync(0xffffffffu, s, o);
    if ((tid & 31) == 0) wred[tid >> 5] = s;
    __syncthreads();
    if (tid == 0) {
        double bs = 0.0;
        #pragma unroll
        for (int i = 0; i < TX / 32; ++i) bs += (double)wred[i];
        const int bid = blockIdx.x + GX * (blockIdx.y + GY * blockIdx.z);
        g_part[bid] = bs;
        __threadfence();
        int old = atomicAdd(&g_cnt, 1);
        slast = (old == NBLK - 1) ? 1 : 0;
    }
    __syncthreads();

    // ---- last block finalizes (deterministic fixed-order double sum) ----
    if (slast) {
        __threadfence();
        double v = 0.0;
        #pragma unroll
        for (int i = 0; i < NBLK / TX; ++i)
            v += g_part[tid + i * TX];
        #pragma unroll
        for (int o = 16; o > 0; o >>= 1) v += __shfl_xor_sync(0xffffffffu, v, o);
        __shared__ double sh[TX / 32];
        if ((tid & 31) == 0) sh[tid >> 5] = v;
        __syncthreads();
        if (tid == 0) {
            double tot = 0.0;
            #pragma unroll
            for (int i = 0; i < TX / 32; ++i) tot += sh[i];
            out[0] = (float)(1.0 - tot / ((double)NIMG * (double)PIX));
            g_cnt = 0;   // self-reset for graph replay
        }
    }
}

extern "C" void kernel_launch(void* const* d_in, const int* in_sizes, int n_in,
                              void* d_out, int out_size)
{
    const float* pred = (const float*)d_in[0];
    const float* gt   = (const float*)d_in[1];
    float* out = (float*)d_out;

    dim3 grid(GX, GY, GZ);
    ssim_main<<<grid, TX>>>(pred, gt, out);
}